// round 10
// baseline (speedup 1.0000x reference)
#include <cuda_runtime.h>
#include <cuda_fp16.h>
#include <math.h>
#include <stdint.h>

// ---------------------------------------------------------------------------
// MoEGate (DeepSeek-V3 noaux_tc router) on GB300 sm_103a (compute_103 PTX)
// Round 10: round-9 numerics (fp16 2-way split, 3 products, hh/corr/master
//           with exact 2Sum drains) with BOTH operands pre-split to fp16
//           planes in global memory. GEMM staging = pure cp.async; single
//           barrier per tile; stage(t+1) overlaps mma(t). Removes register
//           spills (pf/split temps gone) and the serial stage phase.
// ---------------------------------------------------------------------------

#define SEQ     16384
#define HIDDEN  7168
#define NEXP    256
#define NGROUP  8
#define TOPKG   4
#define TOPK    8
#define RSCALE  2.5f

#define KTILE   32
#define NTILES  (HIDDEN / KTILE)     // 224
#define NTHR    256

// ---- scratch -----
__device__ float g_scores[(size_t)SEQ * NEXP];
// B split planes: [2][NTILES][256 cols][16 words]; word = fp16 pair, swizzled
#define B_TILE_WORDS  (256 * 16)                       // 4096
#define B_PLANE_WORDS ((size_t)NTILES * B_TILE_WORDS)  // 917504
__device__ __align__(16) uint32_t g_Bsplit[2 * B_PLANE_WORDS];
// A split planes: [2][NTILES][SEQ rows][16 words]; same swizzle as smem layout
#define A_PLANE_WORDS ((size_t)NTILES * SEQ * 16)      // 58,720,256 words
__device__ __align__(16) uint32_t g_Asplit[2 * A_PLANE_WORDS];   // ~470 MB

// ---- smem stage layout (words) ----
// A planes: p*2048 for p in {0,1}; B planes: B_OFF + p*2048 for p in {0,1}
#define PLANE     2048
#define B_OFF     4096
#define STG_WORDS 8192
#define SMEM_BYTES (2 * STG_WORDS * 4)   // 64 KB

// ------------------------------- helpers -----------------------------------
__device__ __forceinline__ uint16_t f16u(float x) {
    return __half_as_ushort(__float2half_rn(x));
}
__device__ __forceinline__ float f16f(uint16_t u) {
    return __half2float(__ushort_as_half(u));
}
// 2-way fp16 split: x ~= s0 + s1 * 2^-12  (residual ~2^-23 |x|)
__device__ __forceinline__ void split2(float x, uint16_t& s0, uint16_t& s1) {
    s0 = f16u(x);
    const float r = x - f16f(s0);       // exact (Sterbenz)
    s1 = f16u(r * 4096.0f);
}
// non-volatile: lets ptxas interleave HMMA with LDS / cp.async issue
__device__ __forceinline__ void mma16(float* d, const uint32_t* a,
                                      uint32_t b0, uint32_t b1) {
    asm("mma.sync.aligned.m16n8k16.row.col.f32.f16.f16.f32 "
        "{%0,%1,%2,%3}, {%4,%5,%6,%7}, {%8,%9}, {%0,%1,%2,%3};"
        : "+f"(d[0]), "+f"(d[1]), "+f"(d[2]), "+f"(d[3])
        : "r"(a[0]), "r"(a[1]), "r"(a[2]), "r"(a[3]), "r"(b0), "r"(b1));
}
__device__ __forceinline__ void cp16(uint32_t dst, const void* src) {
    asm volatile("cp.async.cg.shared.global [%0], [%1], 16;" :: "r"(dst), "l"(src));
}
// exact 2Sum: master += hh; residual * 4096 accumulated into corr; hh = 0.
__device__ __forceinline__ void twosum_acc(float& master, float& corr, float& hh) {
    float a = master, b = hh, s, bp, ap, da, db, r;
    asm("add.rn.f32 %0, %1, %2;" : "=f"(s)  : "f"(a),  "f"(b));
    asm("sub.rn.f32 %0, %1, %2;" : "=f"(bp) : "f"(s),  "f"(a));
    asm("sub.rn.f32 %0, %1, %2;" : "=f"(ap) : "f"(s),  "f"(bp));
    asm("sub.rn.f32 %0, %1, %2;" : "=f"(db) : "f"(b),  "f"(bp));
    asm("sub.rn.f32 %0, %1, %2;" : "=f"(da) : "f"(a),  "f"(ap));
    asm("add.rn.f32 %0, %1, %2;" : "=f"(r)  : "f"(da), "f"(db));
    asm("fma.rn.f32 %0, %1, 0f45800000, %0;" : "+f"(corr) : "f"(r)); // corr += r*4096
    master = s;
    hh = 0.0f;
}

// ------------------------- W split (pre-swizzled planes) -------------------
// plane0 = fp16(64w), plane1 = fp16((64w - p0)*2^12)
__global__ void wsplit_kernel(const float* __restrict__ W) {
    const int n = blockIdx.x;
    const int k = blockIdx.y * 256 + threadIdx.x;
    const float bp = W[(size_t)n * HIDDEN + k] * 64.0f;
    uint16_t s0, s1;
    split2(bp, s0, s1);
    const int t    = k >> 5;
    const int pair = (k & 31) >> 1;
    const int half = k & 1;
    const uint32_t v  = (uint32_t)(((n >> 1) & 3) << 2);
    const uint32_t wi = (size_t)t * B_TILE_WORDS + (uint32_t)n * 16u
                        + ((uint32_t)pair ^ v);
    uint16_t* base = (uint16_t*)g_Bsplit;
    base[(size_t)0 * B_PLANE_WORDS * 2 + (size_t)wi * 2 + half] = s0;
    base[(size_t)1 * B_PLANE_WORDS * 2 + (size_t)wi * 2 + half] = s1;
}

// ------------------------- A split (pre-swizzled planes) -------------------
// plane0 = fp16(a), plane1 = fp16((a - p0)*2^12); layout [t][row][16 words]
__global__ void asplit_kernel(const float* __restrict__ A) {
    const int row = blockIdx.x;
    const int k   = blockIdx.y * 256 + threadIdx.x;
    const float a = A[(size_t)row * HIDDEN + k];
    uint16_t s0, s1;
    split2(a, s0, s1);
    const int t    = k >> 5;
    const int pair = (k & 31) >> 1;
    const int half = k & 1;
    const uint32_t vr = (uint32_t)(((row >> 1) & 3) << 2);
    const size_t wi = ((size_t)t * SEQ + (size_t)row) * 16 + ((uint32_t)pair ^ vr);
    uint16_t* base = (uint16_t*)g_Asplit;
    base[(size_t)0 * A_PLANE_WORDS * 2 + wi * 2 + half] = s0;
    base[(size_t)1 * A_PLANE_WORDS * 2 + wi * 2 + half] = s1;
}

// ------------------------------- GEMM kernel -------------------------------
__global__ __launch_bounds__(NTHR, 1)
void gemm_fp16_kernel(void) {
    extern __shared__ uint32_t sm[];
    const int tid  = threadIdx.x;
    const int wid  = tid >> 5;
    const int lane = tid & 31;
    const int n0   = blockIdx.x * 128;
    const int m0   = blockIdx.y * 128;

    uint32_t smAddr;
    asm("{ .reg .u64 t; cvta.to.shared.u64 t, %1; cvt.u32.u64 %0, t; }"
        : "=r"(smAddr) : "l"((const void*)sm));

    // ---- staging mappings: thread copies 32 B per plane for A and for B
    const int r = tid >> 1;                  // A row / B col (0..127)
    const int h = tid & 1;                   // 8-word half of the 16-word row
    const uint32_t rowOff = (uint32_t)r * 16u + (uint32_t)h * 8u;
    const size_t aSrcBase = ((size_t)m0 + r) * 16 + h * 8;   // + t*SEQ*16
    const size_t bSrcBase = ((size_t)(n0 + r)) * 16 + h * 8; // + t*B_TILE_WORDS

    // ---- frag mappings: warp grid 4m x 2n, warp tile m32 x n64
    const int wm = wid & 3;
    const int wn = wid >> 2;
    const int qq = lane >> 2;
    const int c  = lane & 3;
    const uint32_t v = (uint32_t)(((qq >> 1) & 3) << 2);
    const uint32_t aRowW = ((uint32_t)wm * 32 + (uint32_t)qq) * 16u;
    const uint32_t bColW = (uint32_t)wn * 1024u + (uint32_t)qq * 16u;

    float hh[16][4];
    float corr[16][4];
    float master[16][4];
    #pragma unroll
    for (int fi = 0; fi < 16; fi++)
        #pragma unroll
        for (int j = 0; j < 4; j++) {
            hh[fi][j] = 0.0f; corr[fi][j] = 0.0f; master[fi][j] = 0.0f;
        }

    // stage tile t into buffer buf (pure cp.async, 8x16B per thread)
    auto stage = [&](int t, int buf) {
        const uint32_t sb = smAddr + (uint32_t)(buf * STG_WORDS) * 4u;
        #pragma unroll
        for (int p = 0; p < 2; p++) {
            const uint32_t* asrc = g_Asplit + (size_t)p * A_PLANE_WORDS
                                 + (size_t)t * (SEQ * 16) + aSrcBase;
            const uint32_t* bsrc = g_Bsplit + (size_t)p * B_PLANE_WORDS
                                 + (size_t)t * B_TILE_WORDS + bSrcBase;
            const uint32_t adst = sb + (p * PLANE + rowOff) * 4u;
            const uint32_t bdst = sb + (B_OFF + p * PLANE + rowOff) * 4u;
            cp16(adst,      asrc);
            cp16(adst + 16, asrc + 4);
            cp16(bdst,      bsrc);
            cp16(bdst + 16, bsrc + 4);
        }
        asm volatile("cp.async.commit_group;");
    };

    // ---- prologue: stage tile 0
    stage(0, 0);

    #pragma unroll 1
    for (int t = 0; t < NTILES; ++t) {
        uint32_t* S = sm + (t & 1) * STG_WORDS;

        asm volatile("cp.async.wait_group 0;");   // tile t data arrived
        __syncthreads();                          // visible to all; mma(t-1) done

        if (t + 1 < NTILES)
            stage(t + 1, (t + 1) & 1);            // overlaps with mma(t)

        // ---- 2 k-steps (k16): per n-frag, 2 m-frags x 3 products
        #pragma unroll
        for (int ks = 0; ks < 2; ks++) {
            const uint32_t o1 = ((uint32_t)(8 * ks + c)) ^ v;
            const uint32_t o2 = o1 ^ 4u;
            uint32_t A0[2][2][4];   // [plane][mfrag][word]
            #pragma unroll
            for (int p = 0; p < 2; p++)
                #pragma unroll
                for (int m = 0; m < 2; m++) {
                    const uint32_t ab = (uint32_t)p * PLANE + aRowW + (uint32_t)m * 256u;
                    A0[p][m][0] = S[ab + o1];
                    A0[p][m][1] = S[ab + 128 + o1];
                    A0[p][m][2] = S[ab + o2];
                    A0[p][m][3] = S[ab + 128 + o2];
                }
            #pragma unroll
            for (int nf = 0; nf < 8; nf++) {
                const uint32_t bb = B_OFF + bColW + (uint32_t)nf * 128u;
                const uint32_t b00 = S[bb + o1];
                const uint32_t b01 = S[bb + o2];
                const uint32_t b10 = S[PLANE + bb + o1];
                const uint32_t b11 = S[PLANE + bb + o2];
                #pragma unroll
                for (int m = 0; m < 2; m++) {
                    const int fi = nf * 2 + m;
                    mma16(hh[fi],   A0[0][m], b00, b01); // a0*b0
                    mma16(corr[fi], A0[0][m], b10, b11); // a0*b1
                    mma16(corr[fi], A0[1][m], b00, b01); // a1*b0
                }
            }
        }

        // ---- exact drain hh -> master every 4 tiles (56x)
        if ((t & 3) == 3) {
            #pragma unroll
            for (int fi = 0; fi < 16; fi++)
                #pragma unroll
                for (int j = 0; j < 4; j++)
                    twosum_acc(master[fi][j], corr[fi][j], hh[fi][j]);
        }
    }

    // ---- epilogue: fp64 combine (undo scales) + sigmoid, direct stores
    #pragma unroll
    for (int fi = 0; fi < 16; fi++) {
        const int nf = fi >> 1;
        const int m  = fi & 1;
        const int r1 = m0 + wm * 32 + m * 16 + qq;
        const int r2 = r1 + 8;
        const int cc = n0 + wn * 64 + nf * 8 + c * 2;
        double lg[4];
        #pragma unroll
        for (int j = 0; j < 4; j++)
            lg[j] = ((double)master[fi][j]
                   + (double)corr[fi][j] * (1.0 / 4096.0)) * (1.0 / 64.0);
        float2 v1, v2;
        v1.x = (float)(1.0 / (1.0 + exp(-lg[0])));
        v1.y = (float)(1.0 / (1.0 + exp(-lg[1])));
        v2.x = (float)(1.0 / (1.0 + exp(-lg[2])));
        v2.y = (float)(1.0 / (1.0 + exp(-lg[3])));
        *(float2*)&g_scores[(size_t)r1 * NEXP + cc] = v1;
        *(float2*)&g_scores[(size_t)r2 * NEXP + cc] = v2;
    }
}

// ----------------------------- Top-k kernel --------------------------------
__global__ __launch_bounds__(256)
void topk_kernel(const float* __restrict__ bias,
                 float* __restrict__ out,
                 int write_idx)
{
    const int warp = threadIdx.x >> 5;
    const int lane = threadIdx.x & 31;
    const int row  = blockIdx.x * 8 + warp;
    if (row >= SEQ) return;

    const float* sp = g_scores + (size_t)row * NEXP + lane * 8;
    const float4 sA = *(const float4*)sp;
    const float4 sB = *(const float4*)(sp + 4);
    float sv[8] = {sA.x, sA.y, sA.z, sA.w, sB.x, sB.y, sB.z, sB.w};

    float c[8];
    #pragma unroll
    for (int i = 0; i < 8; i++)
        c[i] = sv[i] + __ldg(&bias[lane * 8 + i]);

    float m1 = -INFINITY, m2 = -INFINITY;
    #pragma unroll
    for (int i = 0; i < 8; i++) {
        if (c[i] > m1)      { m2 = m1; m1 = c[i]; }
        else if (c[i] > m2) { m2 = c[i]; }
    }
    #pragma unroll
    for (int off = 1; off <= 2; off <<= 1) {
        const float o1 = __shfl_xor_sync(0xFFFFFFFFu, m1, off);
        const float o2 = __shfl_xor_sync(0xFFFFFFFFu, m2, off);
        const float n1 = fmaxf(m1, o1);
        const float n2 = fmaxf(fminf(m1, o1), fmaxf(m2, o2));
        m1 = n1; m2 = n2;
    }
    const float gs = m1 + m2;
    const int   g  = lane >> 2;

    int rank = 0;
    #pragma unroll
    for (int hh = 0; hh < NGROUP; hh++) {
        const float gh = __shfl_sync(0xFFFFFFFFu, gs, hh * 4);
        rank += (gh > gs) || (gh == gs && hh < g);
    }
    const bool sel = (rank < TOPKG);

    float tmp[8];
    #pragma unroll
    for (int i = 0; i < 8; i++)
        tmp[i] = sel ? c[i] : 0.0f;

    float wsel[8];
    int   isel[8];
    float wsum = 0.0f;
    #pragma unroll
    for (int t = 0; t < TOPK; t++) {
        float bv = tmp[0];
        int   bi = 0;
        #pragma unroll
        for (int i = 1; i < 8; i++)
            if (tmp[i] > bv) { bv = tmp[i]; bi = i; }
        int   be   = lane * 8 + bi;
        float braw = sv[bi];
        #pragma unroll
        for (int off = 16; off; off >>= 1) {
            const float ov  = __shfl_xor_sync(0xFFFFFFFFu, bv, off);
            const int   oe  = __shfl_xor_sync(0xFFFFFFFFu, be, off);
            const float orw = __shfl_xor_sync(0xFFFFFFFFu, braw, off);
            if (ov > bv || (ov == bv && oe < be)) { bv = ov; be = oe; braw = orw; }
        }
        wsel[t] = braw;
        isel[t] = be;
        wsum += braw;
        if ((be >> 3) == lane) tmp[be & 7] = -INFINITY;
    }

    const float invd = RSCALE / (wsum + 1e-20f);
    if (lane == 0) {
        #pragma unroll
        for (int t = 0; t < TOPK; t++)
            out[(size_t)row * TOPK + t] = wsel[t] * invd;
        if (write_idx) {
            #pragma unroll
            for (int t = 0; t < TOPK; t++)
                out[(size_t)SEQ * TOPK + (size_t)row * TOPK + t] = (float)isel[t];
        }
    }
}

// ----------------------------- launch --------------------------------------
extern "C" void kernel_launch(void* const* d_in, const int* in_sizes, int n_in,
                              void* d_out, int out_size)
{
    const float* hidden = (const float*)d_in[0];
    const float* weight = (const float*)d_in[1];
    const float* bias   = (const float*)d_in[2];
    for (int i = 0; i < n_in; i++) {
        if (in_sizes[i] == SEQ * HIDDEN)       hidden = (const float*)d_in[i];
        else if (in_sizes[i] == NEXP * HIDDEN) weight = (const float*)d_in[i];
        else if (in_sizes[i] == NEXP)          bias   = (const float*)d_in[i];
    }
    float* out = (float*)d_out;

    cudaFuncSetAttribute(gemm_fp16_kernel,
                         cudaFuncAttributeMaxDynamicSharedMemorySize, SMEM_BYTES);

    wsplit_kernel<<<dim3(NEXP, HIDDEN / 256), 256>>>(weight);
    asplit_kernel<<<dim3(SEQ, HIDDEN / 256), 256>>>(hidden);
    gemm_fp16_kernel<<<dim3(NEXP / 128, SEQ / 128), NTHR, SMEM_BYTES>>>();

    const int write_idx = (out_size >= 2 * SEQ * TOPK) ? 1 : 0;
    topk_kernel<<<SEQ / 8, 256>>>(bias, out, write_idx);
}

// round 11
// speedup vs baseline: 1.0827x; 1.0827x over previous
#include <cuda_runtime.h>
#include <cuda_fp16.h>
#include <math.h>
#include <stdint.h>

// ---------------------------------------------------------------------------
// MoEGate (DeepSeek-V3 noaux_tc router) on GB300 sm_103a (compute_103 PTX)
// Round 11: same proven numerics (fp16 2-way split, 3 products, hh/corr/
//           master exact-2Sum). Structural attack on per-tile fixed cost:
//           KTILE=64 (112 tiles), ldmatrix.x4 fragment loads (4x fewer
//           shared-pipe instructions), 8-granule XOR swizzle (conflict-free
//           LDSM), 3-stage cp.async pipeline, flat pre-split A/B planes.
// ---------------------------------------------------------------------------

#define SEQ     16384
#define HIDDEN  7168
#define NEXP    256
#define NGROUP  8
#define TOPKG   4
#define TOPK    8
#define RSCALE  2.5f

#define KTILE   64
#define NTILES  (HIDDEN / KTILE)     // 112
#define NTHR    256

// ---- scratch -----
__device__ float g_scores[(size_t)SEQ * NEXP];
// B planes: [2][NTILES][256 cols][32 words]; row = 32 words, 8-granule swizzle
#define B_TILE_WORDS  (256 * 32)                       // 8192
#define B_PLANE_WORDS ((size_t)NTILES * B_TILE_WORDS)  // 917504
__device__ __align__(16) uint32_t g_Bsplit[2 * B_PLANE_WORDS];
// A planes: [2][NTILES][SEQ rows][32 words]
#define A_PLANE_WORDS ((size_t)NTILES * SEQ * 32)      // 58,720,256
__device__ __align__(16) uint32_t g_Asplit[2 * A_PLANE_WORDS];

// ---- smem: 3 stages x 64 KB (A: 2 planes x 16KB, B at +32KB: 2 x 16KB)
#define STG_BYTES 65536
#define SMEM_BYTES (3 * STG_BYTES)   // 196608

// ------------------------------- helpers -----------------------------------
__device__ __forceinline__ uint16_t f16u(float x) {
    return __half_as_ushort(__float2half_rn(x));
}
__device__ __forceinline__ float f16f(uint16_t u) {
    return __half2float(__ushort_as_half(u));
}
__device__ __forceinline__ void split2(float x, uint16_t& s0, uint16_t& s1) {
    s0 = f16u(x);
    const float r = x - f16f(s0);       // exact (Sterbenz)
    s1 = f16u(r * 4096.0f);
}
__device__ __forceinline__ void mma16(float* d, const uint32_t* a,
                                      uint32_t b0, uint32_t b1) {
    asm("mma.sync.aligned.m16n8k16.row.col.f32.f16.f16.f32 "
        "{%0,%1,%2,%3}, {%4,%5,%6,%7}, {%8,%9}, {%0,%1,%2,%3};"
        : "+f"(d[0]), "+f"(d[1]), "+f"(d[2]), "+f"(d[3])
        : "r"(a[0]), "r"(a[1]), "r"(a[2]), "r"(a[3]), "r"(b0), "r"(b1));
}
#define LDSM4(r0, r1, r2, r3, addr)                                            \
    asm volatile("ldmatrix.sync.aligned.m8n8.x4.shared.b16 {%0,%1,%2,%3}, [%4];" \
        : "=r"(r0), "=r"(r1), "=r"(r2), "=r"(r3) : "r"(addr))
__device__ __forceinline__ void cp16(uint32_t dst, const void* src) {
    asm volatile("cp.async.cg.shared.global [%0], [%1], 16;" :: "r"(dst), "l"(src));
}
// exact 2Sum: master += hh; residual * 4096 accumulated into corr; hh = 0.
__device__ __forceinline__ void twosum_acc(float& master, float& corr, float& hh) {
    float a = master, b = hh, s, bp, ap, da, db, r;
    asm("add.rn.f32 %0, %1, %2;" : "=f"(s)  : "f"(a),  "f"(b));
    asm("sub.rn.f32 %0, %1, %2;" : "=f"(bp) : "f"(s),  "f"(a));
    asm("sub.rn.f32 %0, %1, %2;" : "=f"(ap) : "f"(s),  "f"(bp));
    asm("sub.rn.f32 %0, %1, %2;" : "=f"(db) : "f"(b),  "f"(bp));
    asm("sub.rn.f32 %0, %1, %2;" : "=f"(da) : "f"(a),  "f"(ap));
    asm("add.rn.f32 %0, %1, %2;" : "=f"(r)  : "f"(da), "f"(db));
    asm("fma.rn.f32 %0, %1, 0f45800000, %0;" : "+f"(corr) : "f"(r)); // corr += r*4096
    master = s;
    hh = 0.0f;
}

// ------------------------- W split (pre-swizzled planes) -------------------
// layout [t][col][32 words]; word w stored at w ^ ((col&7)<<2)
__global__ void wsplit_kernel(const float* __restrict__ W) {
    const int n = blockIdx.x;
    const int k = blockIdx.y * 256 + threadIdx.x;
    const float bp = W[(size_t)n * HIDDEN + k] * 64.0f;
    uint16_t s0, s1;
    split2(bp, s0, s1);
    const int t    = k >> 6;
    const int kk   = k & 63;
    const uint32_t word = (uint32_t)(kk >> 1) ^ (uint32_t)((n & 7) << 2);
    const int half = k & 1;
    const size_t wi = (size_t)t * B_TILE_WORDS + (size_t)n * 32 + word;
    uint16_t* base = (uint16_t*)g_Bsplit;
    base[(size_t)0 * B_PLANE_WORDS * 2 + wi * 2 + half] = s0;
    base[(size_t)1 * B_PLANE_WORDS * 2 + wi * 2 + half] = s1;
}

// ------------------------- A split (pre-swizzled planes) -------------------
// layout [t][row][32 words]; one thread handles one 16B granule (8 k)
__global__ void asplit_kernel(const float* __restrict__ A) {
    const int row = blockIdx.x;
    const int gi  = blockIdx.y * 128 + threadIdx.x;   // 0..895
    const int t   = gi >> 3;
    const int g   = gi & 7;
    const float* src = A + (size_t)row * HIDDEN + t * 64 + g * 8;
    const float4 v0 = *(const float4*)src;
    const float4 v1 = *(const float4*)(src + 4);
    const float av[8] = {v0.x, v0.y, v0.z, v0.w, v1.x, v1.y, v1.z, v1.w};
    uint32_t p0[4], p1[4];
    #pragma unroll
    for (int j = 0; j < 4; j++) {
        uint16_t a0, a1, b0, b1;
        split2(av[j * 2],     a0, a1);
        split2(av[j * 2 + 1], b0, b1);
        p0[j] = (uint32_t)a0 | ((uint32_t)b0 << 16);
        p1[j] = (uint32_t)a1 | ((uint32_t)b1 << 16);
    }
    const size_t wbase = ((size_t)t * SEQ + (size_t)row) * 32
                       + (size_t)((g ^ (row & 7)) << 2);
    *(uint4*)&g_Asplit[wbase] = make_uint4(p0[0], p0[1], p0[2], p0[3]);
    *(uint4*)&g_Asplit[A_PLANE_WORDS + wbase] = make_uint4(p1[0], p1[1], p1[2], p1[3]);
}

// ------------------------------- GEMM kernel -------------------------------
__global__ __launch_bounds__(NTHR, 1)
void gemm_fp16_kernel(void) {
    extern __shared__ uint32_t sm[];
    const int tid  = threadIdx.x;
    const int wid  = tid >> 5;
    const int lane = tid & 31;
    const int n0   = blockIdx.x * 128;
    const int m0   = blockIdx.y * 128;

    uint32_t smAddr;
    asm("{ .reg .u64 t; cvta.to.shared.u64 t, %1; cvt.u32.u64 %0, t; }"
        : "=r"(smAddr) : "l"((const void*)sm));

    // ---- frag mappings: warp grid 4m x 2n, warp tile m32 x n64
    const int wm = wid & 3;
    const int wn = wid >> 2;

    // A ldmatrix lane addresses (stage-relative), one per (plane, mfrag).
    // lanes 0-7: rows 0-7 (a0) | 8-15: rows 8-15 (a1) | 16-23: rows 0-7 k-hi
    // (a2) | 24-31: rows 8-15 k-hi (a3). granule(ks) = addr0 ^ (ks<<5).
    uint32_t offA[2][2];
    {
        const int R = wm * 32 + (lane & 7) + ((lane >> 3) & 1) * 8;
        const int gl = lane >> 4;
        #pragma unroll
        for (int p = 0; p < 2; p++)
            #pragma unroll
            for (int m = 0; m < 2; m++) {
                const int Rm = R + m * 16;
                offA[p][m] = (uint32_t)(p * 16384 + Rm * 128
                           + ((gl ^ (Rm & 7)) << 4));
            }
    }
    // B ldmatrix lane addresses, one per (plane, nf-pair q).
    // lanes 0-7: cols 0-7 k-oct0 | 8-15: cols 0-7 k-oct1 | 16-23: cols 8-15
    // oct0 | 24-31: cols 8-15 oct1  => r0,r1 = b0,b1 of nf=2q; r2,r3 = nf=2q+1
    uint32_t offB[2][4];
    {
        const int gl = (lane >> 3) & 1;
        #pragma unroll
        for (int p = 0; p < 2; p++)
            #pragma unroll
            for (int q = 0; q < 4; q++) {
                const int C = wn * 64 + q * 16 + (lane >> 4) * 8 + (lane & 7);
                offB[p][q] = (uint32_t)(32768 + p * 16384 + C * 128
                           + ((gl ^ (C & 7)) << 4));
            }
    }

    float hh[16][4];
    float corr[16][4];
    float master[16][4];
    #pragma unroll
    for (int fi = 0; fi < 16; fi++)
        #pragma unroll
        for (int j = 0; j < 4; j++) {
            hh[fi][j] = 0.0f; corr[fi][j] = 0.0f; master[fi][j] = 0.0f;
        }

    // ---- staging: flat 16 KB per plane per matrix (pre-swizzled in global)
    auto stage = [&](int t, int buf) {
        const uint32_t sb = smAddr + (uint32_t)buf * STG_BYTES;
        #pragma unroll
        for (int p = 0; p < 2; p++) {
            const uint32_t* asrc = g_Asplit + (size_t)p * A_PLANE_WORDS
                                 + ((size_t)t * SEQ + m0) * 32 + tid * 16;
            const uint32_t* bsrc = g_Bsplit + (size_t)p * B_PLANE_WORDS
                                 + (size_t)t * B_TILE_WORDS + (size_t)n0 * 32 + tid * 16;
            const uint32_t adst = sb + (uint32_t)(p * 16384) + (uint32_t)tid * 64u;
            const uint32_t bdst = adst + 32768u;
            cp16(adst,      asrc);      cp16(adst + 16, asrc + 4);
            cp16(adst + 32, asrc + 8);  cp16(adst + 48, asrc + 12);
            cp16(bdst,      bsrc);      cp16(bdst + 16, bsrc + 4);
            cp16(bdst + 32, bsrc + 8);  cp16(bdst + 48, bsrc + 12);
        }
        asm volatile("cp.async.commit_group;");
    };

    // ---- prologue: 2 tiles in flight
    stage(0, 0);
    stage(1, 1);

    #pragma unroll 1
    for (int t = 0; t < NTILES; ++t) {
        if (t + 1 < NTILES) asm volatile("cp.async.wait_group 1;");
        else                asm volatile("cp.async.wait_group 0;");
        __syncthreads();                       // tile t visible; mma(t-1) done

        if (t + 2 < NTILES) stage(t + 2, (t + 2) % 3);   // overlaps mma(t)

        const uint32_t sb = smAddr + (uint32_t)(t % 3) * STG_BYTES;

        // ---- 4 k-steps (k16): ldmatrix frags + 3 products each
        #pragma unroll
        for (int ks = 0; ks < 4; ks++) {
            const uint32_t ksx = (uint32_t)(ks << 5);
            uint32_t Af[2][2][4];
            #pragma unroll
            for (int p = 0; p < 2; p++)
                #pragma unroll
                for (int m = 0; m < 2; m++)
                    LDSM4(Af[p][m][0], Af[p][m][1], Af[p][m][2], Af[p][m][3],
                          sb + (offA[p][m] ^ ksx));
            #pragma unroll
            for (int q = 0; q < 4; q++) {
                uint32_t B0[4], B1[4];
                LDSM4(B0[0], B0[1], B0[2], B0[3], sb + (offB[0][q] ^ ksx));
                LDSM4(B1[0], B1[1], B1[2], B1[3], sb + (offB[1][q] ^ ksx));
                #pragma unroll
                for (int hf = 0; hf < 2; hf++) {
                    const int nf = q * 2 + hf;
                    const uint32_t b00 = B0[hf * 2], b01 = B0[hf * 2 + 1];
                    const uint32_t b10 = B1[hf * 2], b11 = B1[hf * 2 + 1];
                    #pragma unroll
                    for (int m = 0; m < 2; m++) {
                        const int fi = nf * 2 + m;
                        mma16(hh[fi],   Af[0][m], b00, b01); // a0*b0
                        mma16(corr[fi], Af[0][m], b10, b11); // a0*b1
                        mma16(corr[fi], Af[1][m], b00, b01); // a1*b0
                    }
                }
            }
        }

        // ---- exact drain hh -> master every 2 tiles (= every 128 k, 56x)
        if (t & 1) {
            #pragma unroll
            for (int fi = 0; fi < 16; fi++)
                #pragma unroll
                for (int j = 0; j < 4; j++)
                    twosum_acc(master[fi][j], corr[fi][j], hh[fi][j]);
        }
    }

    // ---- epilogue: fp64 combine (undo scales) + sigmoid, direct stores
    const int qq = lane >> 2;
    const int c  = lane & 3;
    #pragma unroll
    for (int fi = 0; fi < 16; fi++) {
        const int nf = fi >> 1;
        const int m  = fi & 1;
        const int r1 = m0 + wm * 32 + m * 16 + qq;
        const int r2 = r1 + 8;
        const int cc = n0 + wn * 64 + nf * 8 + c * 2;
        double lg[4];
        #pragma unroll
        for (int j = 0; j < 4; j++)
            lg[j] = ((double)master[fi][j]
                   + (double)corr[fi][j] * (1.0 / 4096.0)) * (1.0 / 64.0);
        float2 v1, v2;
        v1.x = (float)(1.0 / (1.0 + exp(-lg[0])));
        v1.y = (float)(1.0 / (1.0 + exp(-lg[1])));
        v2.x = (float)(1.0 / (1.0 + exp(-lg[2])));
        v2.y = (float)(1.0 / (1.0 + exp(-lg[3])));
        *(float2*)&g_scores[(size_t)r1 * NEXP + cc] = v1;
        *(float2*)&g_scores[(size_t)r2 * NEXP + cc] = v2;
    }
}

// ----------------------------- Top-k kernel --------------------------------
__global__ __launch_bounds__(256)
void topk_kernel(const float* __restrict__ bias,
                 float* __restrict__ out,
                 int write_idx)
{
    const int warp = threadIdx.x >> 5;
    const int lane = threadIdx.x & 31;
    const int row  = blockIdx.x * 8 + warp;
    if (row >= SEQ) return;

    const float* sp = g_scores + (size_t)row * NEXP + lane * 8;
    const float4 sA = *(const float4*)sp;
    const float4 sB = *(const float4*)(sp + 4);
    float sv[8] = {sA.x, sA.y, sA.z, sA.w, sB.x, sB.y, sB.z, sB.w};

    float c[8];
    #pragma unroll
    for (int i = 0; i < 8; i++)
        c[i] = sv[i] + __ldg(&bias[lane * 8 + i]);

    float m1 = -INFINITY, m2 = -INFINITY;
    #pragma unroll
    for (int i = 0; i < 8; i++) {
        if (c[i] > m1)      { m2 = m1; m1 = c[i]; }
        else if (c[i] > m2) { m2 = c[i]; }
    }
    #pragma unroll
    for (int off = 1; off <= 2; off <<= 1) {
        const float o1 = __shfl_xor_sync(0xFFFFFFFFu, m1, off);
        const float o2 = __shfl_xor_sync(0xFFFFFFFFu, m2, off);
        const float n1 = fmaxf(m1, o1);
        const float n2 = fmaxf(fminf(m1, o1), fmaxf(m2, o2));
        m1 = n1; m2 = n2;
    }
    const float gs = m1 + m2;
    const int   g  = lane >> 2;

    int rank = 0;
    #pragma unroll
    for (int hh = 0; hh < NGROUP; hh++) {
        const float gh = __shfl_sync(0xFFFFFFFFu, gs, hh * 4);
        rank += (gh > gs) || (gh == gs && hh < g);
    }
    const bool sel = (rank < TOPKG);

    float tmp[8];
    #pragma unroll
    for (int i = 0; i < 8; i++)
        tmp[i] = sel ? c[i] : 0.0f;

    float wsel[8];
    int   isel[8];
    float wsum = 0.0f;
    #pragma unroll
    for (int t = 0; t < TOPK; t++) {
        float bv = tmp[0];
        int   bi = 0;
        #pragma unroll
        for (int i = 1; i < 8; i++)
            if (tmp[i] > bv) { bv = tmp[i]; bi = i; }
        int   be   = lane * 8 + bi;
        float braw = sv[bi];
        #pragma unroll
        for (int off = 16; off; off >>= 1) {
            const float ov  = __shfl_xor_sync(0xFFFFFFFFu, bv, off);
            const int   oe  = __shfl_xor_sync(0xFFFFFFFFu, be, off);
            const float orw = __shfl_xor_sync(0xFFFFFFFFu, braw, off);
            if (ov > bv || (ov == bv && oe < be)) { bv = ov; be = oe; braw = orw; }
        }
        wsel[t] = braw;
        isel[t] = be;
        wsum += braw;
        if ((be >> 3) == lane) tmp[be & 7] = -INFINITY;
    }

    const float invd = RSCALE / (wsum + 1e-20f);
    if (lane == 0) {
        #pragma unroll
        for (int t = 0; t < TOPK; t++)
            out[(size_t)row * TOPK + t] = wsel[t] * invd;
        if (write_idx) {
            #pragma unroll
            for (int t = 0; t < TOPK; t++)
                out[(size_t)SEQ * TOPK + (size_t)row * TOPK + t] = (float)isel[t];
        }
    }
}

// ----------------------------- launch --------------------------------------
extern "C" void kernel_launch(void* const* d_in, const int* in_sizes, int n_in,
                              void* d_out, int out_size)
{
    const float* hidden = (const float*)d_in[0];
    const float* weight = (const float*)d_in[1];
    const float* bias   = (const float*)d_in[2];
    for (int i = 0; i < n_in; i++) {
        if (in_sizes[i] == SEQ * HIDDEN)       hidden = (const float*)d_in[i];
        else if (in_sizes[i] == NEXP * HIDDEN) weight = (const float*)d_in[i];
        else if (in_sizes[i] == NEXP)          bias   = (const float*)d_in[i];
    }
    float* out = (float*)d_out;

    cudaFuncSetAttribute(gemm_fp16_kernel,
                         cudaFuncAttributeMaxDynamicSharedMemorySize, SMEM_BYTES);

    wsplit_kernel<<<dim3(NEXP, HIDDEN / 256), 256>>>(weight);
    asplit_kernel<<<dim3(SEQ, HIDDEN / (128 * 8)), 128>>>(hidden);
    gemm_fp16_kernel<<<dim3(NEXP / 128, SEQ / 128), NTHR, SMEM_BYTES>>>();

    const int write_idx = (out_size >= 2 * SEQ * TOPK) ? 1 : 0;
    topk_kernel<<<SEQ / 8, 256>>>(bias, out, write_idx);
}